// round 2
// baseline (speedup 1.0000x reference)
#include <cuda_runtime.h>
#include <cstdint>

// Problem constants
#define GRID7   7
#define NBOX    2
#define NCLS    20
#define DCH     30          // NB*5 + NC
#define NBATCH  8192
#define CELLS   (NBATCH * GRID7 * GRID7)   // 401408
#define TPB     128
#define NBLK    (CELLS / TPB)              // 3136 exactly
#define VEC4    (TPB * DCH / 4)            // 960 float4 per tensor per block

__device__ float g_partials[NBLK];

// ---------------- fast math helpers (MUFU direct) ----------------
__device__ __forceinline__ float ex2f(float x) {
    float y; asm("ex2.approx.f32 %0, %1;" : "=f"(y) : "f"(x)); return y;
}
__device__ __forceinline__ float lg2f(float x) {
    float y; asm("lg2.approx.f32 %0, %1;" : "=f"(y) : "f"(x)); return y;
}
__device__ __forceinline__ float rcpf(float x) {
    float y; asm("rcp.approx.f32 %0, %1;" : "=f"(y) : "f"(x)); return y;
}
__device__ __forceinline__ float sqrtaf(float x) {
    float y; asm("sqrt.approx.f32 %0, %1;" : "=f"(y) : "f"(x)); return y;
}

#define LOG2E 1.4426950408889634f
#define LN2   0.6931471805599453f

// softplus(l) = max(l,0) + log1p(exp(-|l|))  (numerically stable form)
__device__ __forceinline__ float softplusf(float l) {
    return fmaxf(l, 0.0f) + LN2 * lg2f(1.0f + ex2f(-fabsf(l) * LOG2E));
}
__device__ __forceinline__ float sigmoidf(float x) {
    return rcpf(1.0f + ex2f(-x * LOG2E));
}

__device__ __forceinline__ float iou_f(float al, float at, float ar, float ab,
                                       float bl, float bt, float br, float bb) {
    float ltx = fmaxf(al, bl), lty = fmaxf(at, bt);
    float rbx = fminf(ar, br), rby = fminf(ab, bb);
    float w = fmaxf(rbx - ltx, 0.0f), h = fmaxf(rby - lty, 0.0f);
    float inter = w * h;
    float aa = (ar - al) * (ab - at);
    float ba = (br - bl) * (bb - bt);
    return inter * rcpf(aa + ba - inter + 1e-7f);
}

__device__ __forceinline__ float box_loss_f(float px, float py, float spw, float sph,
                                            float gx, float gy, float sgw, float sgh) {
    float dx = px - gx, dy = py - gy, dw = spw - sgw, dh = sph - sgh;
    return dx * dx + dy * dy + dw * dw + dh * dh;
}

// ---------------- main per-cell kernel ----------------
__global__ void __launch_bounds__(TPB) yolo_loss_kernel(
    const float* __restrict__ p, const float* __restrict__ g)
{
    __shared__ float sp[TPB * DCH];   // 15360 B
    __shared__ float sg[TPB * DCH];   // 15360 B
    __shared__ float wsum[TPB / 32];

    const int t = threadIdx.x;
    const int base = blockIdx.x * (TPB * DCH);   // float offset, < 12.1M

    // Coalesced float4 staging: 960 float4 per tensor per block.
    // 7 full passes of 128 threads + 1 half pass (threads 0-63).
    const float4* __restrict__ p4 = reinterpret_cast<const float4*>(p + base);
    const float4* __restrict__ g4 = reinterpret_cast<const float4*>(g + base);
    float4* sp4 = reinterpret_cast<float4*>(sp);
    float4* sg4 = reinterpret_cast<float4*>(sg);
#pragma unroll
    for (int k = 0; k < 8; k++) {
        int idx = t + k * TPB;
        if (idx < VEC4) {
            sp4[idx] = p4[idx];
            sg4[idx] = g4[idx];
        }
    }
    __syncthreads();

    const float* __restrict__ P = sp + t * DCH;
    const float* __restrict__ G = sg + t * DCH;

    const int cell = blockIdx.x * TPB + t;
    const int rem  = cell % 49;
    const float fi = (float)(rem / 7);   // row
    const float fj = (float)(rem % 7);   // col

    const float conf_g = G[8];
    const bool  is_pos = (conf_g > 0.0f);
    const bool  is_neg = (conf_g == 0.0f);

    const float p8 = P[8], p9 = P[9];
    const float sp8 = softplusf(p8);
    const float sp9 = softplusf(p9);

    float acc = 0.0f;
    if (is_neg) acc = 0.5f * (sp8 + sp9);

    if (is_pos) {
        // ---- classification BCE over 20 classes ----
        float cls = 0.0f;
#pragma unroll
        for (int c = 0; c < NCLS; c++) {
            float l = P[10 + c];
            cls += softplusf(l) - l * G[10 + c];
        }

        // ---- boxes ----
        float px0 = sigmoidf(P[0]), py0 = sigmoidf(P[1]), pw0 = P[2], ph0 = P[3];
        float px1 = sigmoidf(P[4]), py1 = sigmoidf(P[5]), pw1 = P[6], ph1 = P[7];
        float gx0 = G[0], gy0 = G[1], gw0 = G[2], gh0 = G[3];
        float gx1 = G[4], gy1 = G[5], gw1 = G[6], gh1 = G[7];

        const float inv7 = (1.0f / 7.0f);
        // p boxes ltrb (stop-grad copy, same values forward)
        float pcx0 = (px0 + fj) * inv7, pcy0 = (py0 + fi) * inv7;
        float pcx1 = (px1 + fj) * inv7, pcy1 = (py1 + fi) * inv7;
        float pl0 = pcx0 - 0.5f * pw0, pr0 = pcx0 + 0.5f * pw0;
        float pt0 = pcy0 - 0.5f * ph0, pb0 = pcy0 + 0.5f * ph0;
        float pl1 = pcx1 - 0.5f * pw1, pr1 = pcx1 + 0.5f * pw1;
        float pt1 = pcy1 - 0.5f * ph1, pb1 = pcy1 + 0.5f * ph1;
        // g boxes ltrb
        float gcx0 = (gx0 + fj) * inv7, gcy0 = (gy0 + fi) * inv7;
        float gcx1 = (gx1 + fj) * inv7, gcy1 = (gy1 + fi) * inv7;
        float gl0 = gcx0 - 0.5f * gw0, gr0 = gcx0 + 0.5f * gw0;
        float gt0 = gcy0 - 0.5f * gh0, gb0 = gcy0 + 0.5f * gh0;
        float gl1 = gcx1 - 0.5f * gw1, gr1 = gcx1 + 0.5f * gw1;
        float gt1 = gcy1 - 0.5f * gh1, gb1 = gcy1 + 0.5f * gh1;

        // iou[pi][gi]; argmax over pi, first-index wins on ties (strict >)
        float i00 = iou_f(pl0, pt0, pr0, pb0, gl0, gt0, gr0, gb0);
        float i10 = iou_f(pl1, pt1, pr1, pb1, gl0, gt0, gr0, gb0);
        float i01 = iou_f(pl0, pt0, pr0, pb0, gl1, gt1, gr1, gb1);
        float i11 = iou_f(pl1, pt1, pr1, pb1, gl1, gt1, gr1, gb1);
        int ind0 = (i10 > i00);
        int ind1 = (i11 > i01);

        // sqrt precompute for box loss
        float spw0 = sqrtaf(fabsf(pw0)), sph0 = sqrtaf(fabsf(ph0));
        float spw1 = sqrtaf(fabsf(pw1)), sph1 = sqrtaf(fabsf(ph1));
        float sgw0 = sqrtaf(gw0), sgh0 = sqrtaf(gh0);
        float sgw1 = sqrtaf(gw1), sgh1 = sqrtaf(gh1);

        float bl00 = box_loss_f(px0, py0, spw0, sph0, gx0, gy0, sgw0, sgh0);
        float bl10 = box_loss_f(px1, py1, spw1, sph1, gx0, gy0, sgw0, sgh0);
        float bl01 = box_loss_f(px0, py0, spw0, sph0, gx1, gy1, sgw1, sgh1);
        float bl11 = box_loss_f(px1, py1, spw1, sph1, gx1, gy1, sgw1, sgh1);

        float blA  = ind0 ? bl10 : bl00;   // bl(ind0, 0)
        float blC1 = ind1 ? bl11 : bl01;   // bl(ind1, 1)

        bool same_g   = (gx0 == gx1) && (gy0 == gy1) && (gw0 == gw1) && (gh0 == gh1);
        bool same_ind = (ind0 == ind1);

        float lossA = blA;
        float lossB = bl00 + bl11;
        float lossC = blA + blC1;
        float box_cell = same_g ? lossA : (same_ind ? lossB : lossC);

        // conf positive: bce(x, 1) = softplus(x) - x
        float confA  = ind1 ? (sp9 - p9) : (sp8 - p8);
        float confBC = (sp8 - p8) + (sp9 - p9);
        float conf_cell = same_g ? confA : confBC;

        acc += 5.0f * box_cell + conf_cell + cls;
    }

    // ---- deterministic block reduction ----
#pragma unroll
    for (int o = 16; o > 0; o >>= 1)
        acc += __shfl_down_sync(0xFFFFFFFFu, acc, o);
    if ((t & 31) == 0) wsum[t >> 5] = acc;
    __syncthreads();
    if (t == 0) {
        float s = 0.0f;
#pragma unroll
        for (int w = 0; w < TPB / 32; w++) s += wsum[w];
        g_partials[blockIdx.x] = s;
    }
}

// ---------------- final deterministic reduction ----------------
__global__ void __launch_bounds__(256) yolo_finalize_kernel(float* __restrict__ out)
{
    __shared__ float wsum[8];
    const int t = threadIdx.x;
    float s = 0.0f;
    for (int k = t; k < NBLK; k += 256) s += g_partials[k];
#pragma unroll
    for (int o = 16; o > 0; o >>= 1)
        s += __shfl_down_sync(0xFFFFFFFFu, s, o);
    if ((t & 31) == 0) wsum[t >> 5] = s;
    __syncthreads();
    if (t == 0) {
        float tot = 0.0f;
#pragma unroll
        for (int w = 0; w < 8; w++) tot += wsum[w];
        out[0] = tot * (1.0f / (float)NBATCH);
    }
}

extern "C" void kernel_launch(void* const* d_in, const int* in_sizes, int n_in,
                              void* d_out, int out_size)
{
    const float* p = (const float*)d_in[0];
    const float* g = (const float*)d_in[1];
    float* out = (float*)d_out;
    yolo_loss_kernel<<<NBLK, TPB>>>(p, g);
    yolo_finalize_kernel<<<1, 256>>>(out);
}

// round 4
// speedup vs baseline: 1.0884x; 1.0884x over previous
#include <cuda_runtime.h>
#include <cstdint>

// Problem constants
#define GRID7   7
#define NBOX    2
#define NCLS    20
#define DCH     30          // NB*5 + NC
#define NBATCH  8192
#define CELLS   (NBATCH * GRID7 * GRID7)   // 401408
#define TPB     128
#define NBLK    (CELLS / TPB)              // 3136 exactly
#define VEC4    (TPB * DCH / 4)            // 960 float4 per tensor per block
#define NBLK4   (NBLK / 4)                 // 784 float4 partials

__device__ float g_partials[NBLK];
__device__ unsigned int g_count;           // zero-initialized; reset by last block each launch

// ---------------- fast math helpers (MUFU direct) ----------------
__device__ __forceinline__ float ex2f(float x) {
    float y; asm("ex2.approx.f32 %0, %1;" : "=f"(y) : "f"(x)); return y;
}
__device__ __forceinline__ float lg2f(float x) {
    float y; asm("lg2.approx.f32 %0, %1;" : "=f"(y) : "f"(x)); return y;
}
__device__ __forceinline__ float rcpf(float x) {
    float y; asm("rcp.approx.f32 %0, %1;" : "=f"(y) : "f"(x)); return y;
}
__device__ __forceinline__ float sqrtaf(float x) {
    float y; asm("sqrt.approx.f32 %0, %1;" : "=f"(y) : "f"(x)); return y;
}

#define LOG2E 1.4426950408889634f
#define LN2   0.6931471805599453f

// softplus(l) = max(l,0) + log1p(exp(-|l|))  (numerically stable form)
__device__ __forceinline__ float softplusf(float l) {
    return fmaxf(l, 0.0f) + LN2 * lg2f(1.0f + ex2f(-fabsf(l) * LOG2E));
}
__device__ __forceinline__ float sigmoidf(float x) {
    return rcpf(1.0f + ex2f(-x * LOG2E));
}

__device__ __forceinline__ float iou_f(float al, float at, float ar, float ab,
                                       float bl, float bt, float br, float bb) {
    float ltx = fmaxf(al, bl), lty = fmaxf(at, bt);
    float rbx = fminf(ar, br), rby = fminf(ab, bb);
    float w = fmaxf(rbx - ltx, 0.0f), h = fmaxf(rby - lty, 0.0f);
    float inter = w * h;
    float aa = (ar - al) * (ab - at);
    float ba = (br - bl) * (bb - bt);
    return inter * rcpf(aa + ba - inter + 1e-7f);
}

__device__ __forceinline__ float box_loss_f(float px, float py, float spw, float sph,
                                            float gx, float gy, float sgw, float sgh) {
    float dx = px - gx, dy = py - gy, dw = spw - sgw, dh = sph - sgh;
    return dx * dx + dy * dy + dw * dw + dh * dh;
}

// ---------------- fused kernel: per-cell loss + last-block reduction ----------------
__global__ void __launch_bounds__(TPB) yolo_loss_kernel(
    const float* __restrict__ p, const float* __restrict__ g,
    float* __restrict__ out)
{
    __shared__ float sp[TPB * DCH];   // 15360 B
    __shared__ float sg[TPB * DCH];   // 15360 B
    __shared__ float wsum[TPB / 32];
    __shared__ bool  s_is_last;

    const int t = threadIdx.x;
    const int base = blockIdx.x * (TPB * DCH);   // float offset, < 12.1M

    // Coalesced float4 staging: 960 float4 per tensor per block.
    const float4* __restrict__ p4 = reinterpret_cast<const float4*>(p + base);
    const float4* __restrict__ g4 = reinterpret_cast<const float4*>(g + base);
    float4* sp4 = reinterpret_cast<float4*>(sp);
    float4* sg4 = reinterpret_cast<float4*>(sg);
#pragma unroll
    for (int k = 0; k < 8; k++) {
        int idx = t + k * TPB;
        if (idx < VEC4) {
            sp4[idx] = p4[idx];
            sg4[idx] = g4[idx];
        }
    }
    __syncthreads();

    const float* __restrict__ P = sp + t * DCH;
    const float* __restrict__ G = sg + t * DCH;

    const int cell = blockIdx.x * TPB + t;
    const int rem  = cell % 49;
    const float fi = (float)(rem / 7);   // row
    const float fj = (float)(rem % 7);   // col

    const float conf_g = G[8];
    const bool  is_pos = (conf_g > 0.0f);
    const bool  is_neg = (conf_g == 0.0f);

    const float p8 = P[8], p9 = P[9];
    const float sp8 = softplusf(p8);
    const float sp9 = softplusf(p9);

    float acc = 0.0f;
    if (is_neg) acc = 0.5f * (sp8 + sp9);

    if (is_pos) {
        // ---- classification BCE over 20 classes ----
        float cls = 0.0f;
#pragma unroll
        for (int c = 0; c < NCLS; c++) {
            float l = P[10 + c];
            cls += softplusf(l) - l * G[10 + c];
        }

        // ---- boxes ----
        float px0 = sigmoidf(P[0]), py0 = sigmoidf(P[1]), pw0 = P[2], ph0 = P[3];
        float px1 = sigmoidf(P[4]), py1 = sigmoidf(P[5]), pw1 = P[6], ph1 = P[7];
        float gx0 = G[0], gy0 = G[1], gw0 = G[2], gh0 = G[3];
        float gx1 = G[4], gy1 = G[5], gw1 = G[6], gh1 = G[7];

        const float inv7 = (1.0f / 7.0f);
        float pcx0 = (px0 + fj) * inv7, pcy0 = (py0 + fi) * inv7;
        float pcx1 = (px1 + fj) * inv7, pcy1 = (py1 + fi) * inv7;
        float pl0 = pcx0 - 0.5f * pw0, pr0 = pcx0 + 0.5f * pw0;
        float pt0 = pcy0 - 0.5f * ph0, pb0 = pcy0 + 0.5f * ph0;
        float pl1 = pcx1 - 0.5f * pw1, pr1 = pcx1 + 0.5f * pw1;
        float pt1 = pcy1 - 0.5f * ph1, pb1 = pcy1 + 0.5f * ph1;
        float gcx0 = (gx0 + fj) * inv7, gcy0 = (gy0 + fi) * inv7;
        float gcx1 = (gx1 + fj) * inv7, gcy1 = (gy1 + fi) * inv7;
        float gl0 = gcx0 - 0.5f * gw0, gr0 = gcx0 + 0.5f * gw0;
        float gt0 = gcy0 - 0.5f * gh0, gb0 = gcy0 + 0.5f * gh0;
        float gl1 = gcx1 - 0.5f * gw1, gr1 = gcx1 + 0.5f * gw1;
        float gt1 = gcy1 - 0.5f * gh1, gb1 = gcy1 + 0.5f * gh1;

        // iou[pi][gi]; argmax over pi, first-index wins on ties (strict >)
        float i00 = iou_f(pl0, pt0, pr0, pb0, gl0, gt0, gr0, gb0);
        float i10 = iou_f(pl1, pt1, pr1, pb1, gl0, gt0, gr0, gb0);
        float i01 = iou_f(pl0, pt0, pr0, pb0, gl1, gt1, gr1, gb1);
        float i11 = iou_f(pl1, pt1, pr1, pb1, gl1, gt1, gr1, gb1);
        int ind0 = (i10 > i00);
        int ind1 = (i11 > i01);

        float spw0 = sqrtaf(fabsf(pw0)), sph0 = sqrtaf(fabsf(ph0));
        float spw1 = sqrtaf(fabsf(pw1)), sph1 = sqrtaf(fabsf(ph1));
        float sgw0 = sqrtaf(gw0), sgh0 = sqrtaf(gh0);
        float sgw1 = sqrtaf(gw1), sgh1 = sqrtaf(gh1);

        float bl00 = box_loss_f(px0, py0, spw0, sph0, gx0, gy0, sgw0, sgh0);
        float bl10 = box_loss_f(px1, py1, spw1, sph1, gx0, gy0, sgw0, sgh0);
        float bl01 = box_loss_f(px0, py0, spw0, sph0, gx1, gy1, sgw1, sgh1);
        float bl11 = box_loss_f(px1, py1, spw1, sph1, gx1, gy1, sgw1, sgh1);

        float blA  = ind0 ? bl10 : bl00;   // bl(ind0, 0)
        float blC1 = ind1 ? bl11 : bl01;   // bl(ind1, 1)

        bool same_g   = (gx0 == gx1) && (gy0 == gy1) && (gw0 == gw1) && (gh0 == gh1);
        bool same_ind = (ind0 == ind1);

        float lossA = blA;
        float lossB = bl00 + bl11;
        float lossC = blA + blC1;
        float box_cell = same_g ? lossA : (same_ind ? lossB : lossC);

        float confA  = ind1 ? (sp9 - p9) : (sp8 - p8);
        float confBC = (sp8 - p8) + (sp9 - p9);
        float conf_cell = same_g ? confA : confBC;

        acc += 5.0f * box_cell + conf_cell + cls;
    }

    // ---- deterministic block reduction ----
#pragma unroll
    for (int o = 16; o > 0; o >>= 1)
        acc += __shfl_down_sync(0xFFFFFFFFu, acc, o);
    if ((t & 31) == 0) wsum[t >> 5] = acc;
    __syncthreads();
    if (t == 0) {
        float s = 0.0f;
#pragma unroll
        for (int w = 0; w < TPB / 32; w++) s += wsum[w];
        g_partials[blockIdx.x] = s;
        __threadfence();
        unsigned int prev = atomicAdd(&g_count, 1u);
        s_is_last = (prev == (unsigned int)(NBLK - 1));
    }
    __syncthreads();

    // ---- last block: deterministic final reduction over all partials ----
    if (s_is_last) {
        // All 3135 other blocks fenced their partial before incrementing the
        // counter; observing the final count implies all writes are visible.
        const float4* __restrict__ part4 = reinterpret_cast<const float4*>(g_partials);
        float s = 0.0f;
        // NBLK4 = 784 float4 -> 6 full strides of 128 + one partial (16 threads).
#pragma unroll
        for (int k = 0; k < (NBLK4 + TPB - 1) / TPB; k++) {
            int idx = t + k * TPB;
            if (idx < NBLK4) {
                float4 v = part4[idx];
                s += (v.x + v.y) + (v.z + v.w);
            }
        }
#pragma unroll
        for (int o = 16; o > 0; o >>= 1)
            s += __shfl_down_sync(0xFFFFFFFFu, s, o);
        if ((t & 31) == 0) wsum[t >> 5] = s;
        __syncthreads();
        if (t == 0) {
            float tot = 0.0f;
#pragma unroll
            for (int w = 0; w < TPB / 32; w++) tot += wsum[w];
            out[0] = tot * (1.0f / (float)NBATCH);
            g_count = 0;   // reset for next graph replay
        }
    }
}

extern "C" void kernel_launch(void* const* d_in, const int* in_sizes, int n_in,
                              void* d_out, int out_size)
{
    const float* p = (const float*)d_in[0];
    const float* g = (const float*)d_in[1];
    float* out = (float*)d_out;
    yolo_loss_kernel<<<NBLK, TPB>>>(p, g, out);
}